// round 8
// baseline (speedup 1.0000x reference)
#include <cuda_runtime.h>

#define LOG2E 1.44269504088896f
typedef unsigned long long u64;

// Dims: B=2, S=2048, D=1024, H=16, KV=4, QKB=16, VB=32. Rows M=4096.

// -------- scratch --------
__device__ float g_pq[4096 * 256];    // 2*log2e * sigmoid(q)
__device__ float g_pk[4096 * 64];     // sigmoid(k)
__device__ float g_pv[4096 * 128];    // sigmoid(v)
__device__ float g_vh[4096 * 512];    // attention output
__device__ float g_cpart[16 * 1024];
__device__ float g_cvec[1024];        // sum_i e0[i]*Wo[i][j]

// -------- packed f32x2 helpers (Blackwell FFMA2) --------
__device__ __forceinline__ u64 dup2(float x) {
    u64 r; asm("mov.b64 %0, {%1, %1};" : "=l"(r) : "f"(x)); return r;
}
__device__ __forceinline__ u64 pack2(float x, float y) {
    u64 r; asm("mov.b64 %0, {%1, %2};" : "=l"(r) : "f"(x), "f"(y)); return r;
}
__device__ __forceinline__ void unpack2(u64 v, float& x, float& y) {
    asm("mov.b64 {%0, %1}, %2;" : "=f"(x), "=f"(y) : "l"(v));
}
__device__ __forceinline__ void fma2(u64& d, u64 a, u64 b) {
    asm("fma.rn.f32x2 %0, %1, %2, %0;" : "+l"(d) : "l"(a), "l"(b));
}
__device__ __forceinline__ u64 mul2(u64 a, u64 b) {
    u64 r; asm("mul.rn.f32x2 %0, %1, %2;" : "=l"(r) : "l"(a), "l"(b)); return r;
}
__device__ __forceinline__ float ex2f(float x) {
    float r; asm("ex2.approx.ftz.f32 %0, %1;" : "=f"(r) : "f"(x)); return r;
}
__device__ __forceinline__ float sigmoidf_(float x) {
    return 1.0f / (1.0f + __expf(-x));
}

// -------- cvec prep --------
__global__ void prep_cvec1_kernel(const float* __restrict__ Wo,
                                  const float* __restrict__ e0) {
    int ic = blockIdx.x >> 2;
    int j  = (blockIdx.x & 3) * 256 + threadIdx.x;
    float acc = 0.f;
    #pragma unroll
    for (int u = 0; u < 32; u++) {
        int i = ic * 32 + u;
        acc = fmaf(e0[i], Wo[i * 1024 + j], acc);
    }
    g_cpart[ic * 1024 + j] = acc;
}
__global__ void prep_cvec2_kernel() {
    int j = blockIdx.x * 256 + threadIdx.x;
    float acc = 0.f;
    #pragma unroll
    for (int ic = 0; ic < 16; ic++) acc += g_cpart[ic * 1024 + j];
    g_cvec[j] = acc;
}

// -------- QKV GEMM (direct Wq/Wk/Wv reads): hs[4096,1024] @ W[1024,448] --------
// BM=64, BN=128, BK=16, 128 threads, 8x8 micro via f32x2, double-buffered.
__global__ void __launch_bounds__(128, 3) gemm_qkv_kernel(
    const float* __restrict__ A, const float* __restrict__ Wq,
    const float* __restrict__ Wk, const float* __restrict__ Wv)
{
    __shared__ __align__(16) float As[2][16][68];
    __shared__ __align__(16) float Bs[2][16][128];
    const int K = 1024, NT = 64;
    int tid = threadIdx.x;
    int bm = blockIdx.y * 64, bn = blockIdx.x * 128;
    int tx = tid & 15, ty = tid >> 4;
    int arow = tid >> 1, ac8 = (tid & 1) * 8;
    int brow = tid >> 5, bcol = (tid & 31) * 4;

    // per-thread B source column -> matrix map (boundaries 4-aligned)
    int c = bn + bcol;
    const float* bp = Wq; int bstride = 0;
    if      (c < 256) { bp = Wq + c;         bstride = 256; }
    else if (c < 320) { bp = Wk + (c - 256); bstride = 64;  }
    else if (c < 448) { bp = Wv + (c - 320); bstride = 128; }
    bool bvalid = (c < 448);

    const float* abase = &A[(size_t)(bm + arow) * K + ac8];

    float ar[8], br[16];
    *(float4*)&ar[0] = *(const float4*)abase;
    *(float4*)&ar[4] = *(const float4*)(abase + 4);
    #pragma unroll
    for (int i = 0; i < 4; i++) {
        if (bvalid) *(float4*)&br[i * 4] = *(const float4*)&bp[(brow + i * 4) * bstride];
        else { br[i*4] = 0.f; br[i*4+1] = 0.f; br[i*4+2] = 0.f; br[i*4+3] = 0.f; }
    }
    #pragma unroll
    for (int u = 0; u < 8; u++) As[0][ac8 + u][arow] = ar[u];
    #pragma unroll
    for (int i = 0; i < 4; i++) *(float4*)&Bs[0][brow + i * 4][bcol] = *(float4*)&br[i * 4];
    __syncthreads();

    u64 acc[8][4];
    #pragma unroll
    for (int i = 0; i < 8; i++)
        #pragma unroll
        for (int j = 0; j < 4; j++) acc[i][j] = 0ull;

    for (int t = 0; t < NT; t++) {
        int cur = t & 1;
        if (t + 1 < NT) {
            int k0 = (t + 1) * 16;
            *(float4*)&ar[0] = *(const float4*)(abase + k0);
            *(float4*)&ar[4] = *(const float4*)(abase + k0 + 4);
            #pragma unroll
            for (int i = 0; i < 4; i++)
                if (bvalid) *(float4*)&br[i * 4] =
                    *(const float4*)&bp[(k0 + brow + i * 4) * bstride];
        }
        #pragma unroll
        for (int kk = 0; kk < 16; kk++) {
            float a[8];
            *(float4*)&a[0] = *(const float4*)&As[cur][kk][ty * 8];
            *(float4*)&a[4] = *(const float4*)&As[cur][kk][ty * 8 + 4];
            ulonglong2 bA = *(const ulonglong2*)&Bs[cur][kk][tx * 8];
            ulonglong2 bB = *(const ulonglong2*)&Bs[cur][kk][tx * 8 + 4];
            #pragma unroll
            for (int i = 0; i < 8; i++) {
                u64 a2 = dup2(a[i]);
                fma2(acc[i][0], a2, bA.x);
                fma2(acc[i][1], a2, bA.y);
                fma2(acc[i][2], a2, bB.x);
                fma2(acc[i][3], a2, bB.y);
            }
        }
        if (t + 1 < NT) {
            int nxt = cur ^ 1;
            #pragma unroll
            for (int u = 0; u < 8; u++) As[nxt][ac8 + u][arow] = ar[u];
            #pragma unroll
            for (int i = 0; i < 4; i++) *(float4*)&Bs[nxt][brow + i * 4][bcol] = *(float4*)&br[i * 4];
        }
        __syncthreads();
    }

    // epilogue: sigmoid + scatter (8-col chunks never straddle 256/320/448)
    int c0 = bn + tx * 8;
    float* base; int stride, cloc; float osc;
    if      (c0 < 256) { base = g_pq; stride = 256; cloc = c0;       osc = 2.0f * LOG2E; }
    else if (c0 < 320) { base = g_pk; stride = 64;  cloc = c0 - 256; osc = 1.0f; }
    else if (c0 < 448) { base = g_pv; stride = 128; cloc = c0 - 320; osc = 1.0f; }
    else return;
    #pragma unroll
    for (int i = 0; i < 8; i++) {
        float o[8];
        unpack2(acc[i][0], o[0], o[1]); unpack2(acc[i][1], o[2], o[3]);
        unpack2(acc[i][2], o[4], o[5]); unpack2(acc[i][3], o[6], o[7]);
        int row = bm + ty * 8 + i;
        float4 w1, w2;
        w1.x = osc * sigmoidf_(o[0]); w1.y = osc * sigmoidf_(o[1]);
        w1.z = osc * sigmoidf_(o[2]); w1.w = osc * sigmoidf_(o[3]);
        w2.x = osc * sigmoidf_(o[4]); w2.y = osc * sigmoidf_(o[5]);
        w2.z = osc * sigmoidf_(o[6]); w2.w = osc * sigmoidf_(o[7]);
        *(float4*)&base[(size_t)row * stride + cloc]     = w1;
        *(float4*)&base[(size_t)row * stride + cloc + 4] = w2;
    }
}

// -------- attention: thread = 2 rows x 32 cols, keys serial from smem, no shuffles --------
// grid: (8 row-blocks of 256, 32 b*h). 128 threads.
__global__ void __launch_bounds__(128, 3) attn_kernel() {
    __shared__ __align__(16) float s_pk[64][16];
    __shared__ __align__(16) float s_pv[64][32];
    __shared__ float s_sk[64];

    int bh = blockIdx.y;
    int b = bh >> 4, h = bh & 15, kvh = h >> 2;
    int blk = 7 - blockIdx.x;                  // heavy CTAs first
    int tid = threadIdx.x;
    int row0 = blk * 256 + tid * 2;
    int s0 = b * 2048 + row0;
    int wbase = blk * 256 + ((tid >> 5) << 6); // warp's min row
    int wmax  = wbase + 63;                    // warp's max row

    u64 q2[2][8];
    #pragma unroll
    for (int r = 0; r < 2; r++) {
        const float* qp = &g_pq[(size_t)(s0 + r) * 256 + h * 16];
        #pragma unroll
        for (int u = 0; u < 4; u++) {
            ulonglong2 t = *(const ulonglong2*)(qp + u * 4);
            q2[r][2 * u] = t.x; q2[r][2 * u + 1] = t.y;
        }
    }

    u64 vh2[2][16];
    #pragma unroll
    for (int r = 0; r < 2; r++)
        #pragma unroll
        for (int j = 0; j < 16; j++) vh2[r][j] = 0ull;
    float den0 = 0.f, den1 = 0.f;

    const float* gpk = &g_pk[(size_t)(b * 2048) * 64 + kvh * 16];
    const float* gpv = &g_pv[(size_t)(b * 2048) * 128 + kvh * 32];

    int ntiles = 4 * blk + 4;
    for (int t = 0; t < ntiles; t++) {
        int k0 = t * 64;
        __syncthreads();
        {   // cooperative load; fold pk row-sums
            int key = tid >> 1, hf = tid & 1;
            const float* src = &gpk[(size_t)(k0 + key) * 64 + hf * 8];
            float4 p0 = *(const float4*)src, p1 = *(const float4*)(src + 4);
            *(float4*)&s_pk[key][hf * 8]     = p0;
            *(float4*)&s_pk[key][hf * 8 + 4] = p1;
            float ps = p0.x + p0.y + p0.z + p0.w + p1.x + p1.y + p1.z + p1.w;
            ps += __shfl_xor_sync(0xffffffffu, ps, 1);
            if (!hf) s_sk[key] = ps * LOG2E;
            const float* vs = &gpv[(size_t)(k0 + key) * 128 + hf * 16];
            #pragma unroll
            for (int u = 0; u < 4; u++)
                *(float4*)&s_pv[key][hf * 16 + u * 4] = *(const float4*)(vs + u * 4);
        }
        __syncthreads();

        int kcnt = wmax + 1 - k0; if (kcnt > 64) kcnt = 64;
        if (kcnt <= 0) continue;
        bool fullt = (k0 + 63) <= wbase;
        int klim = fullt ? 64 : kcnt;

        for (int k = 0; k < klim; k++) {
            u64 kf2[8];
            const ulonglong2* kp = (const ulonglong2*)&s_pk[k][0];
            ulonglong2 k01 = kp[0], k23 = kp[1], k45 = kp[2], k67 = kp[3];
            kf2[0] = k01.x; kf2[1] = k01.y; kf2[2] = k23.x; kf2[3] = k23.y;
            kf2[4] = k45.x; kf2[5] = k45.y; kf2[6] = k67.x; kf2[7] = k67.y;
            float nsk = s_sk[k];
            u64 y20 = pack2(-nsk, 0.f);
            u64 y21 = y20;
            #pragma unroll
            for (int j = 0; j < 8; j++) {
                fma2(y20, q2[0][j], kf2[j]);
                fma2(y21, q2[1][j], kf2[j]);
            }
            float ya, yb;
            unpack2(y20, ya, yb); float e0 = ex2f(ya + yb);
            unpack2(y21, ya, yb); float e1 = ex2f(ya + yb);
            if (!fullt) {
                int kk = k0 + k;
                e0 = (kk <= row0)     ? e0 : 0.f;
                e1 = (kk <= row0 + 1) ? e1 : 0.f;
            }
            den0 += e0; den1 += e1;
            u64 ed0 = dup2(e0), ed1 = dup2(e1);
            const ulonglong2* vp = (const ulonglong2*)&s_pv[k][0];
            #pragma unroll
            for (int j = 0; j < 8; j++) {
                ulonglong2 vv = vp[j];
                fma2(vh2[0][2 * j],     ed0, vv.x);
                fma2(vh2[0][2 * j + 1], ed0, vv.y);
                fma2(vh2[1][2 * j],     ed1, vv.x);
                fma2(vh2[1][2 * j + 1], ed1, vv.y);
            }
        }
    }

    float* op0 = &g_vh[(size_t)s0 * 512 + h * 32];
    u64 i20 = dup2(1.0f / den0), i21 = dup2(1.0f / den1);
    #pragma unroll
    for (int j = 0; j < 8; j++) {
        ulonglong2 o0, o1;
        o0.x = mul2(vh2[0][2 * j], i20); o0.y = mul2(vh2[0][2 * j + 1], i20);
        o1.x = mul2(vh2[1][2 * j], i21); o1.y = mul2(vh2[1][2 * j + 1], i21);
        *(ulonglong2*)(op0 + j * 4)       = o0;
        *(ulonglong2*)(op0 + 512 + j * 4) = o1;
    }
}

// -------- out GEMM: g_vh[4096,512] @ ((e1-e0)[k]*Wo[k])[512,1024] + cvec --------
// BM=128, BN=128, BK=16, 256 threads, 8x8 micro via f32x2, double-buffered.
__global__ void __launch_bounds__(256, 2) gemm_out_kernel(
    float* __restrict__ C, const float* __restrict__ Wo,
    const float* __restrict__ e0v, const float* __restrict__ e1v)
{
    __shared__ __align__(16) float As[2][16][132];
    __shared__ __align__(16) float Bs[2][16][128];
    const int K = 512, NT = 32, N = 1024;
    int tid = threadIdx.x;
    int bm = blockIdx.y * 128, bn = blockIdx.x * 128;
    int tx = tid & 15, ty = tid >> 4;
    int arow = tid >> 1, ac8 = (tid & 1) * 8;
    int brow = tid >> 5, bcol = (tid & 31) * 4;

    const float* abase = &g_vh[(size_t)(bm + arow) * K + ac8];

    float ar[8], br[8];
    *(float4*)&ar[0] = *(const float4*)abase;
    *(float4*)&ar[4] = *(const float4*)(abase + 4);
    #pragma unroll
    for (int i = 0; i < 2; i++) {
        int r = brow + i * 8;
        float sc = e1v[r] - e0v[r];
        float4 w = *(const float4*)&Wo[(size_t)r * N + bn + bcol];
        br[i*4] = w.x * sc; br[i*4+1] = w.y * sc; br[i*4+2] = w.z * sc; br[i*4+3] = w.w * sc;
    }
    #pragma unroll
    for (int u = 0; u < 8; u++) As[0][ac8 + u][arow] = ar[u];
    #pragma unroll
    for (int i = 0; i < 2; i++) *(float4*)&Bs[0][brow + i * 8][bcol] = *(float4*)&br[i * 4];
    __syncthreads();

    u64 acc[8][4];
    #pragma unroll
    for (int i = 0; i < 8; i++)
        #pragma unroll
        for (int j = 0; j < 4; j++) acc[i][j] = 0ull;

    for (int t = 0; t < NT; t++) {
        int cur = t & 1;
        if (t + 1 < NT) {
            int k0 = (t + 1) * 16;
            *(float4*)&ar[0] = *(const float4*)(abase + k0);
            *(float4*)&ar[4] = *(const float4*)(abase + k0 + 4);
            #pragma unroll
            for (int i = 0; i < 2; i++) {
                int r = k0 + brow + i * 8;
                float sc = e1v[r] - e0v[r];
                float4 w = *(const float4*)&Wo[(size_t)r * N + bn + bcol];
                br[i*4] = w.x * sc; br[i*4+1] = w.y * sc; br[i*4+2] = w.z * sc; br[i*4+3] = w.w * sc;
            }
        }
        #pragma unroll
        for (int kk = 0; kk < 16; kk++) {
            float a[8];
            *(float4*)&a[0] = *(const float4*)&As[cur][kk][ty * 8];
            *(float4*)&a[4] = *(const float4*)&As[cur][kk][ty * 8 + 4];
            ulonglong2 bA = *(const ulonglong2*)&Bs[cur][kk][tx * 8];
            ulonglong2 bB = *(const ulonglong2*)&Bs[cur][kk][tx * 8 + 4];
            #pragma unroll
            for (int i = 0; i < 8; i++) {
                u64 a2 = dup2(a[i]);
                fma2(acc[i][0], a2, bA.x);
                fma2(acc[i][1], a2, bA.y);
                fma2(acc[i][2], a2, bB.x);
                fma2(acc[i][3], a2, bB.y);
            }
        }
        if (t + 1 < NT) {
            int nxt = cur ^ 1;
            #pragma unroll
            for (int u = 0; u < 8; u++) As[nxt][ac8 + u][arow] = ar[u];
            #pragma unroll
            for (int i = 0; i < 2; i++) *(float4*)&Bs[nxt][brow + i * 8][bcol] = *(float4*)&br[i * 4];
        }
        __syncthreads();
    }

    float4 cva = *(const float4*)&g_cvec[bn + tx * 8];
    float4 cvb = *(const float4*)&g_cvec[bn + tx * 8 + 4];
    #pragma unroll
    for (int i = 0; i < 8; i++) {
        float o[8];
        unpack2(acc[i][0], o[0], o[1]); unpack2(acc[i][1], o[2], o[3]);
        unpack2(acc[i][2], o[4], o[5]); unpack2(acc[i][3], o[6], o[7]);
        int row = bm + ty * 8 + i;
        float4 w1 = make_float4(o[0] + cva.x, o[1] + cva.y, o[2] + cva.z, o[3] + cva.w);
        float4 w2 = make_float4(o[4] + cvb.x, o[5] + cvb.y, o[6] + cvb.z, o[7] + cvb.w);
        *(float4*)&C[(size_t)row * N + bn + tx * 8]     = w1;
        *(float4*)&C[(size_t)row * N + bn + tx * 8 + 4] = w2;
    }
}

extern "C" void kernel_launch(void* const* d_in, const int* in_sizes, int n_in,
                              void* d_out, int out_size) {
    (void)in_sizes; (void)n_in; (void)out_size;
    const float* hs = (const float*)d_in[0];
    const float* Wq = (const float*)d_in[1];
    const float* Wk = (const float*)d_in[2];
    const float* Wv = (const float*)d_in[3];
    const float* Wo = (const float*)d_in[4];
    const float* e0 = (const float*)d_in[5];
    const float* e1 = (const float*)d_in[6];
    float* out = (float*)d_out;

    prep_cvec1_kernel<<<64, 256>>>(Wo, e0);
    prep_cvec2_kernel<<<4, 256>>>();
    gemm_qkv_kernel<<<dim3(4, 64), 128>>>(hs, Wq, Wk, Wv);
    attn_kernel<<<dim3(8, 32), 128>>>();
    gemm_out_kernel<<<dim3(8, 32), 256>>>(out, Wo, e0, e1);
}

// round 9
// speedup vs baseline: 1.3185x; 1.3185x over previous
#include <cuda_runtime.h>

#define LOG2E 1.44269504088896f
typedef unsigned long long u64;

// Dims: B=2, S=2048, D=1024, H=16, KV=4, QKB=16, VB=32. Rows M=4096.

// -------- scratch --------
__device__ float g_pq[4096 * 256];    // 2*log2e * sigmoid(q)
__device__ float g_pk[4096 * 64];     // sigmoid(k)
__device__ float g_pv[4096 * 128];    // sigmoid(v)
__device__ float g_vh[4096 * 512];    // attention output (combined)
__device__ float g_part[32 * 8 * 2048 * 32];  // vh partials [bh][slot][s][32]
__device__ float g_pden[32 * 8 * 2048];       // den partials [bh][slot][s]
__device__ float g_cpart[16 * 1024];
__device__ float g_cvec[1024];        // sum_i e0[i]*Wo[i][j]

// -------- packed f32x2 helpers (Blackwell FFMA2) --------
__device__ __forceinline__ u64 dup2(float x) {
    u64 r; asm("mov.b64 %0, {%1, %1};" : "=l"(r) : "f"(x)); return r;
}
__device__ __forceinline__ u64 pack2(float x, float y) {
    u64 r; asm("mov.b64 %0, {%1, %2};" : "=l"(r) : "f"(x), "f"(y)); return r;
}
__device__ __forceinline__ void unpack2(u64 v, float& x, float& y) {
    asm("mov.b64 {%0, %1}, %2;" : "=f"(x), "=f"(y) : "l"(v));
}
__device__ __forceinline__ void fma2(u64& d, u64 a, u64 b) {
    asm("fma.rn.f32x2 %0, %1, %2, %0;" : "+l"(d) : "l"(a), "l"(b));
}
__device__ __forceinline__ float ex2f(float x) {
    float r; asm("ex2.approx.ftz.f32 %0, %1;" : "=f"(r) : "f"(x)); return r;
}
__device__ __forceinline__ float sigmoidf_(float x) {
    return 1.0f / (1.0f + __expf(-x));
}

// -------- cvec prep --------
__global__ void prep_cvec1_kernel(const float* __restrict__ Wo,
                                  const float* __restrict__ e0) {
    int ic = blockIdx.x >> 2;
    int j  = (blockIdx.x & 3) * 256 + threadIdx.x;
    float acc = 0.f;
    #pragma unroll
    for (int u = 0; u < 32; u++) {
        int i = ic * 32 + u;
        acc = fmaf(e0[i], Wo[i * 1024 + j], acc);
    }
    g_cpart[ic * 1024 + j] = acc;
}
__global__ void prep_cvec2_kernel() {
    int j = blockIdx.x * 256 + threadIdx.x;
    float acc = 0.f;
    #pragma unroll
    for (int ic = 0; ic < 16; ic++) acc += g_cpart[ic * 1024 + j];
    g_cvec[j] = acc;
}

// -------- QKV GEMM (direct Wq/Wk/Wv reads): hs[4096,1024] @ W[1024,448] --------
__global__ void __launch_bounds__(128, 3) gemm_qkv_kernel(
    const float* __restrict__ A, const float* __restrict__ Wq,
    const float* __restrict__ Wk, const float* __restrict__ Wv)
{
    __shared__ __align__(16) float As[2][16][68];
    __shared__ __align__(16) float Bs[2][16][128];
    const int K = 1024, NT = 64;
    int tid = threadIdx.x;
    int bm = blockIdx.y * 64, bn = blockIdx.x * 128;
    int tx = tid & 15, ty = tid >> 4;
    int arow = tid >> 1, ac8 = (tid & 1) * 8;
    int brow = tid >> 5, bcol = (tid & 31) * 4;

    int c = bn + bcol;
    const float* bp = Wq; int bstride = 0;
    if      (c < 256) { bp = Wq + c;         bstride = 256; }
    else if (c < 320) { bp = Wk + (c - 256); bstride = 64;  }
    else if (c < 448) { bp = Wv + (c - 320); bstride = 128; }
    bool bvalid = (c < 448);

    const float* abase = &A[(size_t)(bm + arow) * K + ac8];

    float ar[8], br[16];
    *(float4*)&ar[0] = *(const float4*)abase;
    *(float4*)&ar[4] = *(const float4*)(abase + 4);
    #pragma unroll
    for (int i = 0; i < 4; i++) {
        if (bvalid) *(float4*)&br[i * 4] = *(const float4*)&bp[(brow + i * 4) * bstride];
        else { br[i*4] = 0.f; br[i*4+1] = 0.f; br[i*4+2] = 0.f; br[i*4+3] = 0.f; }
    }
    #pragma unroll
    for (int u = 0; u < 8; u++) As[0][ac8 + u][arow] = ar[u];
    #pragma unroll
    for (int i = 0; i < 4; i++) *(float4*)&Bs[0][brow + i * 4][bcol] = *(float4*)&br[i * 4];
    __syncthreads();

    u64 acc[8][4];
    #pragma unroll
    for (int i = 0; i < 8; i++)
        #pragma unroll
        for (int j = 0; j < 4; j++) acc[i][j] = 0ull;

    for (int t = 0; t < NT; t++) {
        int cur = t & 1;
        if (t + 1 < NT) {
            int k0 = (t + 1) * 16;
            *(float4*)&ar[0] = *(const float4*)(abase + k0);
            *(float4*)&ar[4] = *(const float4*)(abase + k0 + 4);
            #pragma unroll
            for (int i = 0; i < 4; i++)
                if (bvalid) *(float4*)&br[i * 4] =
                    *(const float4*)&bp[(k0 + brow + i * 4) * bstride];
        }
        #pragma unroll
        for (int kk = 0; kk < 16; kk++) {
            float a[8];
            *(float4*)&a[0] = *(const float4*)&As[cur][kk][ty * 8];
            *(float4*)&a[4] = *(const float4*)&As[cur][kk][ty * 8 + 4];
            ulonglong2 bA = *(const ulonglong2*)&Bs[cur][kk][tx * 8];
            ulonglong2 bB = *(const ulonglong2*)&Bs[cur][kk][tx * 8 + 4];
            #pragma unroll
            for (int i = 0; i < 8; i++) {
                u64 a2 = dup2(a[i]);
                fma2(acc[i][0], a2, bA.x);
                fma2(acc[i][1], a2, bA.y);
                fma2(acc[i][2], a2, bB.x);
                fma2(acc[i][3], a2, bB.y);
            }
        }
        if (t + 1 < NT) {
            int nxt = cur ^ 1;
            #pragma unroll
            for (int u = 0; u < 8; u++) As[nxt][ac8 + u][arow] = ar[u];
            #pragma unroll
            for (int i = 0; i < 4; i++) *(float4*)&Bs[nxt][brow + i * 4][bcol] = *(float4*)&br[i * 4];
        }
        __syncthreads();
    }

    int c0 = bn + tx * 8;
    float* base; int stride, cloc; float osc;
    if      (c0 < 256) { base = g_pq; stride = 256; cloc = c0;       osc = 2.0f * LOG2E; }
    else if (c0 < 320) { base = g_pk; stride = 64;  cloc = c0 - 256; osc = 1.0f; }
    else if (c0 < 448) { base = g_pv; stride = 128; cloc = c0 - 320; osc = 1.0f; }
    else return;
    #pragma unroll
    for (int i = 0; i < 8; i++) {
        float o[8];
        unpack2(acc[i][0], o[0], o[1]); unpack2(acc[i][1], o[2], o[3]);
        unpack2(acc[i][2], o[4], o[5]); unpack2(acc[i][3], o[6], o[7]);
        int row = bm + ty * 8 + i;
        float4 w1, w2;
        w1.x = osc * sigmoidf_(o[0]); w1.y = osc * sigmoidf_(o[1]);
        w1.z = osc * sigmoidf_(o[2]); w1.w = osc * sigmoidf_(o[3]);
        w2.x = osc * sigmoidf_(o[4]); w2.y = osc * sigmoidf_(o[5]);
        w2.z = osc * sigmoidf_(o[6]); w2.w = osc * sigmoidf_(o[7]);
        *(float4*)&base[(size_t)row * stride + cloc]     = w1;
        *(float4*)&base[(size_t)row * stride + cloc + 4] = w2;
    }
}

// -------- attention partials: CTA = (256 rows) x (256-key chunk), uniform work --------
// grid.x = 36 lower-triangle (rb, c) pairs; grid.y = 32 bh. 128 threads; thread = 2 rows.
__global__ void __launch_bounds__(128) attn_part_kernel() {
    __shared__ __align__(16) float s_pk[64][16];
    __shared__ __align__(16) float s_pv[64][32];
    __shared__ float s_sk[64];

    int bh = blockIdx.y;
    int b = bh >> 4, h = bh & 15, kvh = h >> 2;

    // decode lower-triangle index: i -> (rb, c), c <= rb
    int i = blockIdx.x;
    int rb = 0;
    while ((rb + 1) * (rb + 2) / 2 <= i) rb++;
    int c = i - rb * (rb + 1) / 2;

    int tid = threadIdx.x;
    int row0 = rb * 256 + tid * 2;
    int s0 = b * 2048 + row0;
    int wbase = rb * 256 + ((tid >> 5) << 6);
    int wmax  = wbase + 63;

    u64 q2[2][8];
    #pragma unroll
    for (int r = 0; r < 2; r++) {
        const float* qp = &g_pq[(size_t)(s0 + r) * 256 + h * 16];
        #pragma unroll
        for (int u = 0; u < 4; u++) {
            ulonglong2 t = *(const ulonglong2*)(qp + u * 4);
            q2[r][2 * u] = t.x; q2[r][2 * u + 1] = t.y;
        }
    }

    u64 vh2[2][16];
    #pragma unroll
    for (int r = 0; r < 2; r++)
        #pragma unroll
        for (int j = 0; j < 16; j++) vh2[r][j] = 0ull;
    float den0 = 0.f, den1 = 0.f;

    const float* gpk = &g_pk[(size_t)(b * 2048) * 64 + kvh * 16];
    const float* gpv = &g_pv[(size_t)(b * 2048) * 128 + kvh * 32];

    #pragma unroll 1
    for (int tt = 0; tt < 4; tt++) {
        int k0 = c * 256 + tt * 64;
        __syncthreads();
        {   // cooperative tile load; fold pk row-sums
            int key = tid >> 1, hf = tid & 1;
            const float* src = &gpk[(size_t)(k0 + key) * 64 + hf * 8];
            float4 p0 = *(const float4*)src, p1 = *(const float4*)(src + 4);
            *(float4*)&s_pk[key][hf * 8]     = p0;
            *(float4*)&s_pk[key][hf * 8 + 4] = p1;
            float ps = p0.x + p0.y + p0.z + p0.w + p1.x + p1.y + p1.z + p1.w;
            ps += __shfl_xor_sync(0xffffffffu, ps, 1);
            if (!hf) s_sk[key] = ps * LOG2E;
            const float* vs = &gpv[(size_t)(k0 + key) * 128 + hf * 16];
            #pragma unroll
            for (int u = 0; u < 4; u++)
                *(float4*)&s_pv[key][hf * 16 + u * 4] = *(const float4*)(vs + u * 4);
        }
        __syncthreads();

        if (k0 > wmax) continue;                 // keys beyond this warp's rows
        bool fullt = (k0 + 63) <= wbase;         // no masking needed
        int klim = fullt ? 64 : (wmax + 1 - k0 < 64 ? wmax + 1 - k0 : 64);

        for (int k = 0; k < klim; k++) {
            u64 kf2[8];
            const ulonglong2* kp = (const ulonglong2*)&s_pk[k][0];
            ulonglong2 k01 = kp[0], k23 = kp[1], k45 = kp[2], k67 = kp[3];
            kf2[0] = k01.x; kf2[1] = k01.y; kf2[2] = k23.x; kf2[3] = k23.y;
            kf2[4] = k45.x; kf2[5] = k45.y; kf2[6] = k67.x; kf2[7] = k67.y;
            float nsk = s_sk[k];
            u64 y20 = pack2(-nsk, 0.f);
            u64 y21 = y20;
            #pragma unroll
            for (int j = 0; j < 8; j++) {
                fma2(y20, q2[0][j], kf2[j]);
                fma2(y21, q2[1][j], kf2[j]);
            }
            float ya, yb;
            unpack2(y20, ya, yb); float e0 = ex2f(ya + yb);
            unpack2(y21, ya, yb); float e1 = ex2f(ya + yb);
            if (!fullt) {
                int kk = k0 + k;
                e0 = (kk <= row0)     ? e0 : 0.f;
                e1 = (kk <= row0 + 1) ? e1 : 0.f;
            }
            den0 += e0; den1 += e1;
            u64 ed0 = dup2(e0), ed1 = dup2(e1);
            const ulonglong2* vp = (const ulonglong2*)&s_pv[k][0];
            #pragma unroll
            for (int j = 0; j < 8; j++) {
                ulonglong2 vv = vp[j];
                fma2(vh2[0][2 * j],     ed0, vv.x);
                fma2(vh2[0][2 * j + 1], ed0, vv.y);
                fma2(vh2[1][2 * j],     ed1, vv.x);
                fma2(vh2[1][2 * j + 1], ed1, vv.y);
            }
        }
    }

    // write partials (slot = c): vh raw sums + den
    int srow = (bh * 8 + c) * 2048 + row0;       // [bh][slot][s]
    g_pden[srow]     = den0;
    g_pden[srow + 1] = den1;
    float* pp = &g_part[(size_t)srow * 32];
    #pragma unroll
    for (int j = 0; j < 8; j++) {
        *(ulonglong2*)(pp + j * 4)      = make_ulonglong2(vh2[0][2*j], vh2[0][2*j+1]);
        *(ulonglong2*)(pp + 32 + j * 4) = make_ulonglong2(vh2[1][2*j], vh2[1][2*j+1]);
    }
}

// -------- combine partials: g_vh[row] = sum_slots vh / sum_slots den --------
// thread = 1 row x 8 cols. grid 1024 x 256 threads.
__global__ void __launch_bounds__(256) attn_combine_kernel() {
    int gt = blockIdx.x * 256 + threadIdx.x;     // 262144
    int row = gt >> 2;                           // bh*2048 + s
    int c8 = (gt & 3) * 8;
    int bh = row >> 11, s = row & 2047;
    int nslots = (s >> 8) + 1;

    float den = 0.f;
    float acc[8] = {0.f, 0.f, 0.f, 0.f, 0.f, 0.f, 0.f, 0.f};
    for (int sl = 0; sl < nslots; sl++) {
        int sb = (bh * 8 + sl) * 2048 + s;
        den += g_pden[sb];
        const float4* p = (const float4*)&g_part[(size_t)sb * 32 + c8];
        float4 a = p[0], b2 = p[1];
        acc[0] += a.x;  acc[1] += a.y;  acc[2] += a.z;  acc[3] += a.w;
        acc[4] += b2.x; acc[5] += b2.y; acc[6] += b2.z; acc[7] += b2.w;
    }
    float inv = 1.0f / den;
    int b = bh >> 4, h = bh & 15;
    float* o = &g_vh[(size_t)(b * 2048 + s) * 512 + h * 32 + c8];
    float4 w1 = make_float4(acc[0]*inv, acc[1]*inv, acc[2]*inv, acc[3]*inv);
    float4 w2 = make_float4(acc[4]*inv, acc[5]*inv, acc[6]*inv, acc[7]*inv);
    *(float4*)o       = w1;
    *(float4*)(o + 4) = w2;
}

// -------- out GEMM: g_vh[4096,512] @ ((e1-e0)[k]*Wo[k])[512,1024] + cvec --------
__global__ void __launch_bounds__(256, 2) gemm_out_kernel(
    float* __restrict__ C, const float* __restrict__ Wo,
    const float* __restrict__ e0v, const float* __restrict__ e1v)
{
    __shared__ __align__(16) float As[2][16][132];
    __shared__ __align__(16) float Bs[2][16][128];
    const int K = 512, NT = 32, N = 1024;
    int tid = threadIdx.x;
    int bm = blockIdx.y * 128, bn = blockIdx.x * 128;
    int tx = tid & 15, ty = tid >> 4;
    int arow = tid >> 1, ac8 = (tid & 1) * 8;
    int brow = tid >> 5, bcol = (tid & 31) * 4;

    const float* abase = &g_vh[(size_t)(bm + arow) * K + ac8];

    float ar[8], br[8];
    *(float4*)&ar[0] = *(const float4*)abase;
    *(float4*)&ar[4] = *(const float4*)(abase + 4);
    #pragma unroll
    for (int i = 0; i < 2; i++) {
        int r = brow + i * 8;
        float sc = e1v[r] - e0v[r];
        float4 w = *(const float4*)&Wo[(size_t)r * N + bn + bcol];
        br[i*4] = w.x * sc; br[i*4+1] = w.y * sc; br[i*4+2] = w.z * sc; br[i*4+3] = w.w * sc;
    }
    #pragma unroll
    for (int u = 0; u < 8; u++) As[0][ac8 + u][arow] = ar[u];
    #pragma unroll
    for (int i = 0; i < 2; i++) *(float4*)&Bs[0][brow + i * 8][bcol] = *(float4*)&br[i * 4];
    __syncthreads();

    u64 acc[8][4];
    #pragma unroll
    for (int i = 0; i < 8; i++)
        #pragma unroll
        for (int j = 0; j < 4; j++) acc[i][j] = 0ull;

    for (int t = 0; t < NT; t++) {
        int cur = t & 1;
        if (t + 1 < NT) {
            int k0 = (t + 1) * 16;
            *(float4*)&ar[0] = *(const float4*)(abase + k0);
            *(float4*)&ar[4] = *(const float4*)(abase + k0 + 4);
            #pragma unroll
            for (int i = 0; i < 2; i++) {
                int r = k0 + brow + i * 8;
                float sc = e1v[r] - e0v[r];
                float4 w = *(const float4*)&Wo[(size_t)r * N + bn + bcol];
                br[i*4] = w.x * sc; br[i*4+1] = w.y * sc; br[i*4+2] = w.z * sc; br[i*4+3] = w.w * sc;
            }
        }
        #pragma unroll
        for (int kk = 0; kk < 16; kk++) {
            float a[8];
            *(float4*)&a[0] = *(const float4*)&As[cur][kk][ty * 8];
            *(float4*)&a[4] = *(const float4*)&As[cur][kk][ty * 8 + 4];
            ulonglong2 bA = *(const ulonglong2*)&Bs[cur][kk][tx * 8];
            ulonglong2 bB = *(const ulonglong2*)&Bs[cur][kk][tx * 8 + 4];
            #pragma unroll
            for (int i = 0; i < 8; i++) {
                u64 a2 = dup2(a[i]);
                fma2(acc[i][0], a2, bA.x);
                fma2(acc[i][1], a2, bA.y);
                fma2(acc[i][2], a2, bB.x);
                fma2(acc[i][3], a2, bB.y);
            }
        }
        if (t + 1 < NT) {
            int nxt = cur ^ 1;
            #pragma unroll
            for (int u = 0; u < 8; u++) As[nxt][ac8 + u][arow] = ar[u];
            #pragma unroll
            for (int i = 0; i < 2; i++) *(float4*)&Bs[nxt][brow + i * 8][bcol] = *(float4*)&br[i * 4];
        }
        __syncthreads();
    }

    float4 cva = *(const float4*)&g_cvec[bn + tx * 8];
    float4 cvb = *(const float4*)&g_cvec[bn + tx * 8 + 4];
    #pragma unroll
    for (int i = 0; i < 8; i++) {
        float o[8];
        unpack2(acc[i][0], o[0], o[1]); unpack2(acc[i][1], o[2], o[3]);
        unpack2(acc[i][2], o[4], o[5]); unpack2(acc[i][3], o[6], o[7]);
        int row = bm + ty * 8 + i;
        float4 w1 = make_float4(o[0] + cva.x, o[1] + cva.y, o[2] + cva.z, o[3] + cva.w);
        float4 w2 = make_float4(o[4] + cvb.x, o[5] + cvb.y, o[6] + cvb.z, o[7] + cvb.w);
        *(float4*)&C[(size_t)row * N + bn + tx * 8]     = w1;
        *(float4*)&C[(size_t)row * N + bn + tx * 8 + 4] = w2;
    }
}

extern "C" void kernel_launch(void* const* d_in, const int* in_sizes, int n_in,
                              void* d_out, int out_size) {
    (void)in_sizes; (void)n_in; (void)out_size;
    const float* hs = (const float*)d_in[0];
    const float* Wq = (const float*)d_in[1];
    const float* Wk = (const float*)d_in[2];
    const float* Wv = (const float*)d_in[3];
    const float* Wo = (const float*)d_in[4];
    const float* e0 = (const float*)d_in[5];
    const float* e1 = (const float*)d_in[6];
    float* out = (float*)d_out;

    prep_cvec1_kernel<<<64, 256>>>(Wo, e0);
    prep_cvec2_kernel<<<4, 256>>>();
    gemm_qkv_kernel<<<dim3(4, 64), 128>>>(hs, Wq, Wk, Wv);
    attn_part_kernel<<<dim3(36, 32), 128>>>();
    attn_combine_kernel<<<1024, 256>>>();
    gemm_out_kernel<<<dim3(8, 32), 256>>>(out, Wo, e0, e1);
}